// round 8
// baseline (speedup 1.0000x reference)
#include <cuda_runtime.h>
#include <cstdint>

#define NA 200000
#define NW 50000
#define D 256
#define P 64
#define E_TIC 4000000
#define E_REL 1000000

#define NB_TIC ((NA + 2047) / 2048)   // 98
#define NB_REL ((NW + 2047) / 2048)   // 25

typedef unsigned long long u64;
typedef unsigned int u32;

// ---------------- scratch (device globals: no allocation allowed) ----------
__device__ float g_h_tic[(size_t)NA * P];
__device__ float g_h_rel[(size_t)NA * P];
__device__ float g_acc_tic[(size_t)NA * P];
__device__ float g_acc_rel[(size_t)NW * P];

__device__ int  g_cnt_tic[NA];
__device__ int  g_cnt_rel[NW];
__device__ int  g_start_tic[NA];
__device__ int  g_start_rel[NW];
__device__ int  g_pos_tic[NA];
__device__ int  g_pos_rel[NW];
__device__ int  g_bsum_tic[128];
__device__ int  g_bsum_rel[128];
__device__ u64  g_csr_tic[E_TIC];           // packed (w<<32 | src)
__device__ u64  g_csr_rel[E_REL];

// ---------------- helpers ---------------------------------------------------
__device__ __forceinline__ u32 f2tf32(float f) {
    u32 o; asm("cvt.rna.tf32.f32 %0, %1;" : "=r"(o) : "f"(f)); return o;
}

__device__ __forceinline__ void mma_tf32(float* c, const u32* a, const u32* b) {
    asm volatile(
        "mma.sync.aligned.m16n8k8.row.col.f32.tf32.tf32.f32 "
        "{%0,%1,%2,%3}, {%4,%5,%6,%7}, {%8,%9}, {%0,%1,%2,%3};"
        : "+f"(c[0]), "+f"(c[1]), "+f"(c[2]), "+f"(c[3])
        : "r"(a[0]), "r"(a[1]), "r"(a[2]), "r"(a[3]), "r"(b[0]), "r"(b[1]));
}

__device__ __forceinline__ u64 ldcs64(const u64* p) {
    u64 v; asm("ld.global.cs.b64 %0, [%1];" : "=l"(v) : "l"(p)); return v;
}

// ---------------- CSR build --------------------------------------------------
template <int REL>
__global__ __launch_bounds__(256) void zero_cnt() {
    int i = blockIdx.x * blockDim.x + threadIdx.x;
    const int N = REL ? NW : NA;
    int* cnt = REL ? g_cnt_rel : g_cnt_tic;
    if (i < N) cnt[i] = 0;
}

template <int REL>
__global__ __launch_bounds__(256) void hist(const int* __restrict__ dst, int E) {
    int e4 = (blockIdx.x * blockDim.x + threadIdx.x) * 4;
    if (e4 >= E) return;
    int4 d = __ldg((const int4*)&dst[e4]);
    int* cnt = REL ? g_cnt_rel : g_cnt_tic;
    atomicAdd(&cnt[d.x], 1);
    atomicAdd(&cnt[d.y], 1);
    atomicAdd(&cnt[d.z], 1);
    atomicAdd(&cnt[d.w], 1);
}

template <int REL>
__global__ __launch_bounds__(256) void scan1() {
    const int N = REL ? NW : NA;
    const int* cnt = REL ? g_cnt_rel : g_cnt_tic;
    int* start = REL ? g_start_rel : g_start_tic;
    int* bsum = REL ? g_bsum_rel : g_bsum_tic;

    __shared__ int sh[256];
    int t = threadIdx.x;
    int base = blockIdx.x * 2048 + t * 8;
    int v[8]; int s = 0;
#pragma unroll
    for (int j = 0; j < 8; j++) {
        int idx = base + j;
        int c = (idx < N) ? cnt[idx] : 0;
        v[j] = s; s += c;
    }
    sh[t] = s;
    __syncthreads();
    int own = s;
    for (int off = 1; off < 256; off <<= 1) {
        int y = (t >= off) ? sh[t - off] : 0;
        __syncthreads();
        sh[t] += y;
        __syncthreads();
    }
    int texcl = sh[t] - own;
#pragma unroll
    for (int j = 0; j < 8; j++) {
        int idx = base + j;
        if (idx < N) start[idx] = v[j] + texcl;
    }
    if (t == 255) bsum[blockIdx.x] = sh[255];
}

template <int REL>
__global__ __launch_bounds__(128) void scan2() {
    const int NB = REL ? NB_REL : NB_TIC;
    int* bsum = REL ? g_bsum_rel : g_bsum_tic;
    __shared__ int sh[128];
    int t = threadIdx.x;
    int val = (t < NB) ? bsum[t] : 0;
    sh[t] = val;
    __syncthreads();
    for (int off = 1; off < 128; off <<= 1) {
        int y = (t >= off) ? sh[t - off] : 0;
        __syncthreads();
        sh[t] += y;
        __syncthreads();
    }
    if (t < NB) bsum[t] = sh[t] - val;
}

template <int REL>
__global__ __launch_bounds__(256) void scan3() {
    const int N = REL ? NW : NA;
    int* start = REL ? g_start_rel : g_start_tic;
    int* pos = REL ? g_pos_rel : g_pos_tic;
    const int* bsum = REL ? g_bsum_rel : g_bsum_tic;
    int add = bsum[blockIdx.x];
    int base = blockIdx.x * 2048 + threadIdx.x * 8;
#pragma unroll
    for (int j = 0; j < 8; j++) {
        int idx = base + j;
        if (idx < N) {
            int v = start[idx] + add;
            start[idx] = v;
            pos[idx] = v;
        }
    }
}

template <int REL>
__global__ __launch_bounds__(256) void reorder(const int* __restrict__ src,
                                               const int* __restrict__ dst,
                                               const float* __restrict__ we,
                                               int E) {
    int e4 = (blockIdx.x * blockDim.x + threadIdx.x) * 4;
    if (e4 >= E) return;
    int4 d = __ldg((const int4*)&dst[e4]);
    int4 s = __ldg((const int4*)&src[e4]);
    float4 w = __ldg((const float4*)&we[e4]);
    int* pos = REL ? g_pos_rel : g_pos_tic;
    u64* csr = REL ? g_csr_rel : g_csr_tic;
    int p0 = atomicAdd(&pos[d.x], 1);
    int p1 = atomicAdd(&pos[d.y], 1);
    int p2 = atomicAdd(&pos[d.z], 1);
    int p3 = atomicAdd(&pos[d.w], 1);
    csr[p0] = ((u64)__float_as_uint(w.x) << 32) | (u32)s.x;
    csr[p1] = ((u64)__float_as_uint(w.y) << 32) | (u32)s.y;
    csr[p2] = ((u64)__float_as_uint(w.z) << 32) | (u32)s.z;
    csr[p3] = ((u64)__float_as_uint(w.w) << 32) | (u32)s.w;
}

// ---------------- gather: warp per dst row, half-warps pair edges ----------
// lanes 0-15 process even edges, lanes 16-31 odd edges; each lane loads a
// float4 so one LDG.128 covers a full 256B h-row per half-warp.
template <int REL>
__global__ __launch_bounds__(256) void gather_rows() {
    const int N = REL ? NW : NA;
    const int* start = REL ? g_start_rel : g_start_tic;
    const int* cnt = REL ? g_cnt_rel : g_cnt_tic;
    const u64* csr = REL ? g_csr_rel : g_csr_tic;
    const float* h = REL ? g_h_rel : g_h_tic;
    float* acc = REL ? g_acc_rel : g_acc_tic;

    int r = blockIdx.x * 8 + (threadIdx.x >> 5);
    int lid = threadIdx.x & 31;
    int half = lid >> 4;
    int q = lid & 15;
    if (r >= N) return;
    int beg = start[r];
    int c = cnt[r];
    int end = beg + c;

    float4 a0 = make_float4(0.f, 0.f, 0.f, 0.f);
    float4 a1 = make_float4(0.f, 0.f, 0.f, 0.f);

    int i = beg + half;
    // unrolled x2: this lane covers edges i and i+2 (other half does i+1, i+3)
    for (; i + 2 < end; i += 4) {
        u64 p0 = ldcs64(&csr[i]);
        u64 p1 = ldcs64(&csr[i + 2]);
        float4 h0 = __ldg((const float4*)&h[(size_t)(u32)p0 * P + q * 4]);
        float4 h1 = __ldg((const float4*)&h[(size_t)(u32)p1 * P + q * 4]);
        float w0 = __uint_as_float((u32)(p0 >> 32));
        float w1 = __uint_as_float((u32)(p1 >> 32));
        a0.x += h0.x * w0; a0.y += h0.y * w0; a0.z += h0.z * w0; a0.w += h0.w * w0;
        a1.x += h1.x * w1; a1.y += h1.y * w1; a1.z += h1.z * w1; a1.w += h1.w * w1;
    }
    if (i < end) {
        u64 p = ldcs64(&csr[i]);
        float4 hv = __ldg((const float4*)&h[(size_t)(u32)p * P + q * 4]);
        float w = __uint_as_float((u32)(p >> 32));
        a0.x += hv.x * w; a0.y += hv.y * w; a0.z += hv.z * w; a0.w += hv.w * w;
    }
    a0.x += a1.x; a0.y += a1.y; a0.z += a1.z; a0.w += a1.w;
    // combine the two half-warps (same columns, disjoint edge subsets)
    a0.x += __shfl_xor_sync(0xffffffffu, a0.x, 16);
    a0.y += __shfl_xor_sync(0xffffffffu, a0.y, 16);
    a0.z += __shfl_xor_sync(0xffffffffu, a0.z, 16);
    a0.w += __shfl_xor_sync(0xffffffffu, a0.w, 16);

    if (half == 0) {
        float inv = (c > 0) ? 1.0f / (float)c : 0.0f;
        a0.x *= inv; a0.y *= inv; a0.z *= inv; a0.w *= inv;
        *(float4*)&acc[(size_t)r * P + q * 4] = a0;
    }
}

// ---------------- tf32 mma.sync GEMM ---------------------------------------
// MODE 0: N=128, -> g_h_tic | g_h_rel
// MODE 1: N=64,  out = x @ W_self + b + acc_tic (mean already)
// MODE 2: N=64,  out = 0.5*(x[:, :64] + x @ W_self + b + acc_rel)
template <int N_TILE, int MODE, int WM, int WN>
__global__ __launch_bounds__(256) void gemm_mma(const float* __restrict__ x,
                                                const float* __restrict__ W0,
                                                const float* __restrict__ W1,
                                                const float* __restrict__ b,
                                                float* __restrict__ out,
                                                int nrows) {
    constexpr int WTM = 128 / WM;
    constexpr int WTN = N_TILE / WN;
    constexpr int MT = WTM / 16;
    constexpr int NT = WTN / 8;

    __shared__ u32 A_s[128][36];
    __shared__ u32 B_s[N_TILE][36];
    __shared__ float b_s[P];

    int tid = threadIdx.x;
    int wid = tid >> 5, lid = tid & 31;
    int g = lid >> 2, t4 = lid & 3;
    int wm = wid / WN, wn = wid % WN;
    int m_warp = wm * WTM, n_warp = wn * WTN;
    int row0 = blockIdx.x * 128;

    if (MODE != 0 && tid < P) b_s[tid] = b[tid];

    float acc[MT][NT][4];
#pragma unroll
    for (int i = 0; i < MT; i++)
#pragma unroll
        for (int j = 0; j < NT; j++)
#pragma unroll
            for (int v = 0; v < 4; v++) acc[i][j][v] = 0.f;

    for (int c = 0; c < 8; c++) {
        int k0 = c * 32;
        if (c > 0) __syncthreads();
#pragma unroll
        for (int it = 0; it < 4; it++) {
            int idx = tid + it * 256;
            int m = idx >> 3, q = idx & 7;
            float4 v = make_float4(0.f, 0.f, 0.f, 0.f);
            if (row0 + m < nrows)
                v = *(const float4*)&x[(size_t)(row0 + m) * D + k0 + q * 4];
            uint4 t;
            t.x = f2tf32(v.x); t.y = f2tf32(v.y);
            t.z = f2tf32(v.z); t.w = f2tf32(v.w);
            *(uint4*)&A_s[m][q * 4] = t;
        }
#pragma unroll
        for (int it = 0; it < N_TILE * 32 / 256; it++) {
            int i = tid + it * 256;
            int k = i / N_TILE, n = i % N_TILE;
            float w;
            if (MODE == 0)
                w = (n < P) ? W0[(k0 + k) * P + n] : W1[(k0 + k) * P + (n - P)];
            else
                w = W0[(k0 + k) * P + n];
            B_s[n][k] = f2tf32(w);
        }
        __syncthreads();
#pragma unroll
        for (int ks = 0; ks < 4; ks++) {
            int kk = ks * 8;
            u32 afr[MT][4];
#pragma unroll
            for (int mt = 0; mt < MT; mt++) {
                int m = m_warp + mt * 16 + g;
                afr[mt][0] = A_s[m][kk + t4];
                afr[mt][1] = A_s[m + 8][kk + t4];
                afr[mt][2] = A_s[m][kk + t4 + 4];
                afr[mt][3] = A_s[m + 8][kk + t4 + 4];
            }
            u32 bfr[NT][2];
#pragma unroll
            for (int nt = 0; nt < NT; nt++) {
                int n = n_warp + nt * 8 + g;
                bfr[nt][0] = B_s[n][kk + t4];
                bfr[nt][1] = B_s[n][kk + t4 + 4];
            }
#pragma unroll
            for (int mt = 0; mt < MT; mt++)
#pragma unroll
                for (int nt = 0; nt < NT; nt++)
                    mma_tf32(acc[mt][nt], afr[mt], bfr[nt]);
        }
    }

    if (MODE != 0) __syncthreads();

#pragma unroll
    for (int mt = 0; mt < MT; mt++) {
#pragma unroll
        for (int half = 0; half < 2; half++) {
            int r = row0 + m_warp + mt * 16 + g + half * 8;
            if (r >= nrows) continue;
            const float* accb = (MODE == 1) ? g_acc_tic :
                                (MODE == 2) ? g_acc_rel : nullptr;
#pragma unroll
            for (int nt = 0; nt < NT; nt++) {
                int col = n_warp + nt * 8 + t4 * 2;
                float v0 = acc[mt][nt][half * 2 + 0];
                float v1 = acc[mt][nt][half * 2 + 1];
                if (MODE == 0) {
                    float* dstb = (col < P) ? g_h_tic : g_h_rel;
                    int cc = col & (P - 1);
                    float2 o; o.x = v0; o.y = v1;
                    *(float2*)&dstb[(size_t)r * P + cc] = o;
                } else {
                    float2 av = *(const float2*)&accb[(size_t)r * P + col];
                    v0 += b_s[col] + av.x;
                    v1 += b_s[col + 1] + av.y;
                    if (MODE == 2) {
                        float2 xv = *(const float2*)&x[(size_t)r * D + col];
                        v0 = 0.5f * (xv.x + v0);
                        v1 = 0.5f * (xv.y + v1);
                    }
                    float2 o; o.x = v0; o.y = v1;
                    *(float2*)&out[(size_t)r * P + col] = o;
                }
            }
        }
    }
}

// ---------------- launch: 3-stream DAG --------------------------------------
//  s0: gemm_neigh --------------------(waits tic CSR)--> gather<0> -> gemm_out<0>
//  s1: tic CSR build (zero,hist,scan,reorder) --evC-->
//  s2: rel CSR build ------(waits h)--> gather<1> -> gemm_out<1>
extern "C" void kernel_launch(void* const* d_in, const int* in_sizes, int n_in,
                              void* d_out, int out_size) {
    const float* x_ac        = (const float*)d_in[0];
    const float* x_w         = (const float*)d_in[1];
    const int*   src_tic     = (const int*)d_in[2];
    const int*   dst_tic     = (const int*)d_in[3];
    const float* w_tic       = (const float*)d_in[4];
    const int*   src_rel     = (const int*)d_in[5];
    const int*   dst_rel     = (const int*)d_in[6];
    const float* w_rel       = (const float*)d_in[7];
    const float* W_self_tic  = (const float*)d_in[8];
    const float* W_neigh_tic = (const float*)d_in[9];
    const float* b_tic       = (const float*)d_in[10];
    const float* W_self_rel  = (const float*)d_in[11];
    const float* W_neigh_rel = (const float*)d_in[12];
    const float* b_rel       = (const float*)d_in[13];
    float* out = (float*)d_out;

    static cudaStream_t s1 = nullptr, s2 = nullptr;
    static cudaEvent_t ev0 = nullptr, evC = nullptr, evN = nullptr, evD = nullptr;
    if (s1 == nullptr) {
        cudaStreamCreateWithFlags(&s1, cudaStreamNonBlocking);
        cudaStreamCreateWithFlags(&s2, cudaStreamNonBlocking);
        cudaEventCreateWithFlags(&ev0, cudaEventDisableTiming);
        cudaEventCreateWithFlags(&evC, cudaEventDisableTiming);
        cudaEventCreateWithFlags(&evN, cudaEventDisableTiming);
        cudaEventCreateWithFlags(&evD, cudaEventDisableTiming);
    }

    const int GRID_A = (NA + 127) / 128;
    const int GRID_W = (NW + 127) / 128;

    // fork
    cudaEventRecord(ev0, 0);
    cudaStreamWaitEvent(s1, ev0, 0);
    cudaStreamWaitEvent(s2, ev0, 0);

    // s0: big GEMM producing h_tic / h_rel
    gemm_mma<128, 0, 2, 4><<<GRID_A, 256>>>(x_ac, W_neigh_tic, W_neigh_rel,
                                            nullptr, nullptr, NA);
    cudaEventRecord(evN, 0);

    // s1: tic CSR build
    zero_cnt<0><<<(NA + 255) / 256, 256, 0, s1>>>();
    hist<0><<<(E_TIC / 4 + 255) / 256, 256, 0, s1>>>(dst_tic, E_TIC);
    scan1<0><<<NB_TIC, 256, 0, s1>>>();
    scan2<0><<<1, 128, 0, s1>>>();
    scan3<0><<<NB_TIC, 256, 0, s1>>>();
    reorder<0><<<(E_TIC / 4 + 255) / 256, 256, 0, s1>>>(src_tic, dst_tic, w_tic, E_TIC);
    cudaEventRecord(evC, s1);

    // s2: rel CSR build
    zero_cnt<1><<<(NW + 255) / 256, 256, 0, s2>>>();
    hist<1><<<(E_REL / 4 + 255) / 256, 256, 0, s2>>>(dst_rel, E_REL);
    scan1<1><<<NB_REL, 256, 0, s2>>>();
    scan2<1><<<1, 128, 0, s2>>>();
    scan3<1><<<NB_REL, 256, 0, s2>>>();
    reorder<1><<<(E_REL / 4 + 255) / 256, 256, 0, s2>>>(src_rel, dst_rel, w_rel, E_REL);

    // cross dependencies
    cudaStreamWaitEvent(0, evC, 0);   // gather<0> needs tic CSR
    cudaStreamWaitEvent(s2, evN, 0);  // gather<1> needs h_rel

    gather_rows<0><<<(NA + 7) / 8, 256>>>();
    gather_rows<1><<<(NW + 7) / 8, 256, 0, s2>>>();

    gemm_mma<64, 1, 4, 2><<<GRID_A, 256>>>(x_ac, W_self_tic, nullptr,
                                           b_tic, out, NA);
    gemm_mma<64, 2, 4, 2><<<GRID_W, 256, 0, s2>>>(x_w, W_self_rel, nullptr,
                                                  b_rel, out + (size_t)NA * P, NW);

    // join
    cudaEventRecord(evD, s2);
    cudaStreamWaitEvent(0, evD, 0);
}

// round 9
// speedup vs baseline: 1.0124x; 1.0124x over previous
#include <cuda_runtime.h>
#include <cstdint>

#define NA 200000
#define NW 50000
#define D 256
#define P 64
#define E_TIC 4000000
#define E_REL 1000000

#define NB_TIC ((NA + 2047) / 2048)   // 98
#define NB_REL ((NW + 2047) / 2048)   // 25

typedef unsigned long long u64;
typedef unsigned int u32;

// ---------------- scratch (device globals: no allocation allowed) ----------
__device__ float g_h_tic[(size_t)NA * P];
__device__ float g_h_rel[(size_t)NA * P];
__device__ float g_acc_tic[(size_t)NA * P];
__device__ float g_acc_rel[(size_t)NW * P];

__device__ int  g_cnt_tic[NA];
__device__ int  g_cnt_rel[NW];
__device__ int  g_start_tic[NA];
__device__ int  g_start_rel[NW];
__device__ int  g_pos_tic[NA];
__device__ int  g_pos_rel[NW];
__device__ int  g_bsum_tic[128];
__device__ int  g_bsum_rel[128];
__device__ u64  g_csr_tic[E_TIC];           // packed (w<<32 | src)
__device__ u64  g_csr_rel[E_REL];

// ---------------- helpers ---------------------------------------------------
__device__ __forceinline__ u32 f2tf32(float f) {
    u32 o; asm("cvt.rna.tf32.f32 %0, %1;" : "=r"(o) : "f"(f)); return o;
}

__device__ __forceinline__ void mma_tf32(float* c, const u32* a, const u32* b) {
    asm volatile(
        "mma.sync.aligned.m16n8k8.row.col.f32.tf32.tf32.f32 "
        "{%0,%1,%2,%3}, {%4,%5,%6,%7}, {%8,%9}, {%0,%1,%2,%3};"
        : "+f"(c[0]), "+f"(c[1]), "+f"(c[2]), "+f"(c[3])
        : "r"(a[0]), "r"(a[1]), "r"(a[2]), "r"(a[3]), "r"(b[0]), "r"(b[1]));
}

// ---------------- CSR build --------------------------------------------------
template <int REL>
__global__ __launch_bounds__(256) void zero_cnt() {
    int i = blockIdx.x * blockDim.x + threadIdx.x;
    const int N = REL ? NW : NA;
    int* cnt = REL ? g_cnt_rel : g_cnt_tic;
    if (i < N) cnt[i] = 0;
}

template <int REL>
__global__ __launch_bounds__(256) void hist(const int* __restrict__ dst, int E) {
    int e4 = (blockIdx.x * blockDim.x + threadIdx.x) * 4;
    if (e4 >= E) return;
    int4 d = __ldg((const int4*)&dst[e4]);
    int* cnt = REL ? g_cnt_rel : g_cnt_tic;
    atomicAdd(&cnt[d.x], 1);
    atomicAdd(&cnt[d.y], 1);
    atomicAdd(&cnt[d.z], 1);
    atomicAdd(&cnt[d.w], 1);
}

template <int REL>
__global__ __launch_bounds__(256) void scan1() {
    const int N = REL ? NW : NA;
    const int* cnt = REL ? g_cnt_rel : g_cnt_tic;
    int* start = REL ? g_start_rel : g_start_tic;
    int* bsum = REL ? g_bsum_rel : g_bsum_tic;

    __shared__ int sh[256];
    int t = threadIdx.x;
    int base = blockIdx.x * 2048 + t * 8;
    int v[8]; int s = 0;
#pragma unroll
    for (int j = 0; j < 8; j++) {
        int idx = base + j;
        int c = (idx < N) ? cnt[idx] : 0;
        v[j] = s; s += c;
    }
    sh[t] = s;
    __syncthreads();
    int own = s;
    for (int off = 1; off < 256; off <<= 1) {
        int y = (t >= off) ? sh[t - off] : 0;
        __syncthreads();
        sh[t] += y;
        __syncthreads();
    }
    int texcl = sh[t] - own;
#pragma unroll
    for (int j = 0; j < 8; j++) {
        int idx = base + j;
        if (idx < N) start[idx] = v[j] + texcl;
    }
    if (t == 255) bsum[blockIdx.x] = sh[255];
}

template <int REL>
__global__ __launch_bounds__(128) void scan2() {
    const int NB = REL ? NB_REL : NB_TIC;
    int* bsum = REL ? g_bsum_rel : g_bsum_tic;
    __shared__ int sh[128];
    int t = threadIdx.x;
    int val = (t < NB) ? bsum[t] : 0;
    sh[t] = val;
    __syncthreads();
    for (int off = 1; off < 128; off <<= 1) {
        int y = (t >= off) ? sh[t - off] : 0;
        __syncthreads();
        sh[t] += y;
        __syncthreads();
    }
    if (t < NB) bsum[t] = sh[t] - val;
}

template <int REL>
__global__ __launch_bounds__(256) void scan3() {
    const int N = REL ? NW : NA;
    int* start = REL ? g_start_rel : g_start_tic;
    int* pos = REL ? g_pos_rel : g_pos_tic;
    const int* bsum = REL ? g_bsum_rel : g_bsum_tic;
    int add = bsum[blockIdx.x];
    int base = blockIdx.x * 2048 + threadIdx.x * 8;
#pragma unroll
    for (int j = 0; j < 8; j++) {
        int idx = base + j;
        if (idx < N) {
            int v = start[idx] + add;
            start[idx] = v;
            pos[idx] = v;
        }
    }
}

template <int REL>
__global__ __launch_bounds__(256) void reorder(const int* __restrict__ src,
                                               const int* __restrict__ dst,
                                               const float* __restrict__ we,
                                               int E) {
    int e4 = (blockIdx.x * blockDim.x + threadIdx.x) * 4;
    if (e4 >= E) return;
    int4 d = __ldg((const int4*)&dst[e4]);
    int4 s = __ldg((const int4*)&src[e4]);
    float4 w = __ldg((const float4*)&we[e4]);
    int* pos = REL ? g_pos_rel : g_pos_tic;
    u64* csr = REL ? g_csr_rel : g_csr_tic;
    int p0 = atomicAdd(&pos[d.x], 1);
    int p1 = atomicAdd(&pos[d.y], 1);
    int p2 = atomicAdd(&pos[d.z], 1);
    int p3 = atomicAdd(&pos[d.w], 1);
    csr[p0] = ((u64)__float_as_uint(w.x) << 32) | (u32)s.x;
    csr[p1] = ((u64)__float_as_uint(w.y) << 32) | (u32)s.y;
    csr[p2] = ((u64)__float_as_uint(w.z) << 32) | (u32)s.z;
    csr[p3] = ((u64)__float_as_uint(w.w) << 32) | (u32)s.w;
}

// ---------------- gather v3: warp per dst row -------------------------------
// CSR metadata loaded coalesced (lane l -> edge base+l, one LDG.64 per 32
// edges), broadcast via shfl; h loads unrolled x8 for deep MLP. Each lane
// holds one float2 column pair of the 64-wide row.
template <int REL>
__global__ __launch_bounds__(256) void gather_rows() {
    const int N = REL ? NW : NA;
    const int* start = REL ? g_start_rel : g_start_tic;
    const int* cnt = REL ? g_cnt_rel : g_cnt_tic;
    const u64* csr = REL ? g_csr_rel : g_csr_tic;
    const float2* h2 = (const float2*)(REL ? g_h_rel : g_h_tic);
    float* acc = REL ? g_acc_rel : g_acc_tic;

    int r = blockIdx.x * 8 + (threadIdx.x >> 5);
    int lid = threadIdx.x & 31;
    if (r >= N) return;
    int beg = start[r];
    int c = cnt[r];

    float ax = 0.f, ay = 0.f;
    for (int base = 0; base < c; base += 32) {
        int nn = min(32, c - base);
        u64 meta = 0;
        if (lid < nn) meta = __ldg(&csr[beg + base + lid]);
        int j = 0;
        for (; j + 8 <= nn; j += 8) {
            u64 m[8];
#pragma unroll
            for (int t = 0; t < 8; t++)
                m[t] = __shfl_sync(0xffffffffu, meta, j + t);
            float2 hv[8];
#pragma unroll
            for (int t = 0; t < 8; t++)
                hv[t] = __ldg(&h2[(size_t)(u32)m[t] * 32 + lid]);
#pragma unroll
            for (int t = 0; t < 8; t++) {
                float w = __uint_as_float((u32)(m[t] >> 32));
                ax += hv[t].x * w;
                ay += hv[t].y * w;
            }
        }
        if (j + 4 <= nn) {
            u64 m[4];
#pragma unroll
            for (int t = 0; t < 4; t++)
                m[t] = __shfl_sync(0xffffffffu, meta, j + t);
            float2 hv[4];
#pragma unroll
            for (int t = 0; t < 4; t++)
                hv[t] = __ldg(&h2[(size_t)(u32)m[t] * 32 + lid]);
#pragma unroll
            for (int t = 0; t < 4; t++) {
                float w = __uint_as_float((u32)(m[t] >> 32));
                ax += hv[t].x * w;
                ay += hv[t].y * w;
            }
            j += 4;
        }
        for (; j < nn; j++) {
            u64 m = __shfl_sync(0xffffffffu, meta, j);
            float2 hv = __ldg(&h2[(size_t)(u32)m * 32 + lid]);
            float w = __uint_as_float((u32)(m >> 32));
            ax += hv.x * w;
            ay += hv.y * w;
        }
    }
    float inv = (c > 0) ? 1.0f / (float)c : 0.0f;
    float2 o; o.x = ax * inv; o.y = ay * inv;
    *(float2*)&acc[(size_t)r * P + lid * 2] = o;
}

// ---------------- tf32 mma.sync GEMM ---------------------------------------
// MODE 0: N=128, -> g_h_tic | g_h_rel
// MODE 1: N=64,  out = x @ W_self + b + acc_tic (mean already)
// MODE 2: N=64,  out = 0.5*(x[:, :64] + x @ W_self + b + acc_rel)
template <int N_TILE, int MODE, int WM, int WN>
__global__ __launch_bounds__(256) void gemm_mma(const float* __restrict__ x,
                                                const float* __restrict__ W0,
                                                const float* __restrict__ W1,
                                                const float* __restrict__ b,
                                                float* __restrict__ out,
                                                int nrows) {
    constexpr int WTM = 128 / WM;
    constexpr int WTN = N_TILE / WN;
    constexpr int MT = WTM / 16;
    constexpr int NT = WTN / 8;

    __shared__ u32 A_s[128][36];
    __shared__ u32 B_s[N_TILE][36];
    __shared__ float b_s[P];

    int tid = threadIdx.x;
    int wid = tid >> 5, lid = tid & 31;
    int g = lid >> 2, t4 = lid & 3;
    int wm = wid / WN, wn = wid % WN;
    int m_warp = wm * WTM, n_warp = wn * WTN;
    int row0 = blockIdx.x * 128;

    if (MODE != 0 && tid < P) b_s[tid] = b[tid];

    float acc[MT][NT][4];
#pragma unroll
    for (int i = 0; i < MT; i++)
#pragma unroll
        for (int j = 0; j < NT; j++)
#pragma unroll
            for (int v = 0; v < 4; v++) acc[i][j][v] = 0.f;

    for (int c = 0; c < 8; c++) {
        int k0 = c * 32;
        if (c > 0) __syncthreads();
#pragma unroll
        for (int it = 0; it < 4; it++) {
            int idx = tid + it * 256;
            int m = idx >> 3, q = idx & 7;
            float4 v = make_float4(0.f, 0.f, 0.f, 0.f);
            if (row0 + m < nrows)
                v = *(const float4*)&x[(size_t)(row0 + m) * D + k0 + q * 4];
            uint4 t;
            t.x = f2tf32(v.x); t.y = f2tf32(v.y);
            t.z = f2tf32(v.z); t.w = f2tf32(v.w);
            *(uint4*)&A_s[m][q * 4] = t;
        }
#pragma unroll
        for (int it = 0; it < N_TILE * 32 / 256; it++) {
            int i = tid + it * 256;
            int k = i / N_TILE, n = i % N_TILE;
            float w;
            if (MODE == 0)
                w = (n < P) ? W0[(k0 + k) * P + n] : W1[(k0 + k) * P + (n - P)];
            else
                w = W0[(k0 + k) * P + n];
            B_s[n][k] = f2tf32(w);
        }
        __syncthreads();
#pragma unroll
        for (int ks = 0; ks < 4; ks++) {
            int kk = ks * 8;
            u32 afr[MT][4];
#pragma unroll
            for (int mt = 0; mt < MT; mt++) {
                int m = m_warp + mt * 16 + g;
                afr[mt][0] = A_s[m][kk + t4];
                afr[mt][1] = A_s[m + 8][kk + t4];
                afr[mt][2] = A_s[m][kk + t4 + 4];
                afr[mt][3] = A_s[m + 8][kk + t4 + 4];
            }
            u32 bfr[NT][2];
#pragma unroll
            for (int nt = 0; nt < NT; nt++) {
                int n = n_warp + nt * 8 + g;
                bfr[nt][0] = B_s[n][kk + t4];
                bfr[nt][1] = B_s[n][kk + t4 + 4];
            }
#pragma unroll
            for (int mt = 0; mt < MT; mt++)
#pragma unroll
                for (int nt = 0; nt < NT; nt++)
                    mma_tf32(acc[mt][nt], afr[mt], bfr[nt]);
        }
    }

    if (MODE != 0) __syncthreads();

#pragma unroll
    for (int mt = 0; mt < MT; mt++) {
#pragma unroll
        for (int half = 0; half < 2; half++) {
            int r = row0 + m_warp + mt * 16 + g + half * 8;
            if (r >= nrows) continue;
            const float* accb = (MODE == 1) ? g_acc_tic :
                                (MODE == 2) ? g_acc_rel : nullptr;
#pragma unroll
            for (int nt = 0; nt < NT; nt++) {
                int col = n_warp + nt * 8 + t4 * 2;
                float v0 = acc[mt][nt][half * 2 + 0];
                float v1 = acc[mt][nt][half * 2 + 1];
                if (MODE == 0) {
                    float* dstb = (col < P) ? g_h_tic : g_h_rel;
                    int cc = col & (P - 1);
                    float2 o; o.x = v0; o.y = v1;
                    *(float2*)&dstb[(size_t)r * P + cc] = o;
                } else {
                    float2 av = *(const float2*)&accb[(size_t)r * P + col];
                    v0 += b_s[col] + av.x;
                    v1 += b_s[col + 1] + av.y;
                    if (MODE == 2) {
                        float2 xv = *(const float2*)&x[(size_t)r * D + col];
                        v0 = 0.5f * (xv.x + v0);
                        v1 = 0.5f * (xv.y + v1);
                    }
                    float2 o; o.x = v0; o.y = v1;
                    *(float2*)&out[(size_t)r * P + col] = o;
                }
            }
        }
    }
}

// ---------------- launch: fork-join two-stream DAG --------------------------
//  s0: gemm_neigh ----------(waits tic CSR)--> gather<0> -> gemm_out<0>
//  s1: tic CSR build --evC--> rel CSR build --(waits h)--> gather<1> -> out<1>
extern "C" void kernel_launch(void* const* d_in, const int* in_sizes, int n_in,
                              void* d_out, int out_size) {
    const float* x_ac        = (const float*)d_in[0];
    const float* x_w         = (const float*)d_in[1];
    const int*   src_tic     = (const int*)d_in[2];
    const int*   dst_tic     = (const int*)d_in[3];
    const float* w_tic       = (const float*)d_in[4];
    const int*   src_rel     = (const int*)d_in[5];
    const int*   dst_rel     = (const int*)d_in[6];
    const float* w_rel       = (const float*)d_in[7];
    const float* W_self_tic  = (const float*)d_in[8];
    const float* W_neigh_tic = (const float*)d_in[9];
    const float* b_tic       = (const float*)d_in[10];
    const float* W_self_rel  = (const float*)d_in[11];
    const float* W_neigh_rel = (const float*)d_in[12];
    const float* b_rel       = (const float*)d_in[13];
    float* out = (float*)d_out;

    static cudaStream_t s1 = nullptr;
    static cudaEvent_t ev0 = nullptr, evC = nullptr, evN = nullptr, evD = nullptr;
    if (s1 == nullptr) {
        cudaStreamCreateWithFlags(&s1, cudaStreamNonBlocking);
        cudaEventCreateWithFlags(&ev0, cudaEventDisableTiming);
        cudaEventCreateWithFlags(&evC, cudaEventDisableTiming);
        cudaEventCreateWithFlags(&evN, cudaEventDisableTiming);
        cudaEventCreateWithFlags(&evD, cudaEventDisableTiming);
    }

    const int GRID_A = (NA + 127) / 128;
    const int GRID_W = (NW + 127) / 128;

    // fork
    cudaEventRecord(ev0, 0);
    cudaStreamWaitEvent(s1, ev0, 0);

    // s0: big GEMM producing h_tic / h_rel
    gemm_mma<128, 0, 2, 4><<<GRID_A, 256>>>(x_ac, W_neigh_tic, W_neigh_rel,
                                            nullptr, nullptr, NA);
    cudaEventRecord(evN, 0);

    // s1: tic CSR build first (critical), then rel build
    zero_cnt<0><<<(NA + 255) / 256, 256, 0, s1>>>();
    hist<0><<<(E_TIC / 4 + 255) / 256, 256, 0, s1>>>(dst_tic, E_TIC);
    scan1<0><<<NB_TIC, 256, 0, s1>>>();
    scan2<0><<<1, 128, 0, s1>>>();
    scan3<0><<<NB_TIC, 256, 0, s1>>>();
    reorder<0><<<(E_TIC / 4 + 255) / 256, 256, 0, s1>>>(src_tic, dst_tic, w_tic, E_TIC);
    cudaEventRecord(evC, s1);   // tic CSR ready (rel build NOT on this event)

    zero_cnt<1><<<(NW + 255) / 256, 256, 0, s1>>>();
    hist<1><<<(E_REL / 4 + 255) / 256, 256, 0, s1>>>(dst_rel, E_REL);
    scan1<1><<<NB_REL, 256, 0, s1>>>();
    scan2<1><<<1, 128, 0, s1>>>();
    scan3<1><<<NB_REL, 256, 0, s1>>>();
    reorder<1><<<(E_REL / 4 + 255) / 256, 256, 0, s1>>>(src_rel, dst_rel, w_rel, E_REL);

    // cross dependencies
    cudaStreamWaitEvent(0, evC, 0);   // gather<0> needs tic CSR
    cudaStreamWaitEvent(s1, evN, 0);  // gather<1> needs h_rel

    gather_rows<0><<<(NA + 7) / 8, 256>>>();
    gather_rows<1><<<(NW + 7) / 8, 256, 0, s1>>>();

    gemm_mma<64, 1, 4, 2><<<GRID_A, 256>>>(x_ac, W_self_tic, nullptr,
                                           b_tic, out, NA);
    gemm_mma<64, 2, 4, 2><<<GRID_W, 256, 0, s1>>>(x_w, W_self_rel, nullptr,
                                                  b_rel, out + (size_t)NA * P, NW);

    // join
    cudaEventRecord(evD, s1);
    cudaStreamWaitEvent(0, evD, 0);
}

// round 10
// speedup vs baseline: 1.0926x; 1.0792x over previous
#include <cuda_runtime.h>
#include <cstdint>

#define NA 200000
#define NW 50000
#define D 256
#define P 64
#define E_TIC 4000000
#define E_REL 1000000

#define NB_TIC ((NA + 2047) / 2048)   // 98
#define NB_REL ((NW + 2047) / 2048)   // 25

typedef unsigned long long u64;
typedef unsigned int u32;

// ---------------- scratch (device globals: no allocation allowed) ----------
__device__ float g_h_tic[(size_t)NA * P];
__device__ float g_h_rel[(size_t)NA * P];
__device__ float g_acc_tic[(size_t)NA * P];
__device__ float g_acc_rel[(size_t)NW * P];

__device__ int  g_cnt_tic[NA];
__device__ int  g_cnt_rel[NW];
__device__ int  g_start_tic[NA];
__device__ int  g_start_rel[NW];
__device__ int  g_pos_tic[NA];
__device__ int  g_pos_rel[NW];
__device__ int  g_bsum_tic[128];
__device__ int  g_bsum_rel[128];
__device__ u64  g_csr_tic[E_TIC];           // packed (w<<32 | src)
__device__ u64  g_csr_rel[E_REL];

// ---------------- helpers ---------------------------------------------------
__device__ __forceinline__ u32 f2tf32(float f) {
    u32 o; asm("cvt.rna.tf32.f32 %0, %1;" : "=r"(o) : "f"(f)); return o;
}

__device__ __forceinline__ void mma_tf32(float* c, const u32* a, const u32* b) {
    asm volatile(
        "mma.sync.aligned.m16n8k8.row.col.f32.tf32.tf32.f32 "
        "{%0,%1,%2,%3}, {%4,%5,%6,%7}, {%8,%9}, {%0,%1,%2,%3};"
        : "+f"(c[0]), "+f"(c[1]), "+f"(c[2]), "+f"(c[3])
        : "r"(a[0]), "r"(a[1]), "r"(a[2]), "r"(a[3]), "r"(b[0]), "r"(b[1]));
}

// ---------------- CSR build --------------------------------------------------
template <int REL>
__global__ __launch_bounds__(256) void zero_cnt() {
    int i = blockIdx.x * blockDim.x + threadIdx.x;
    const int N = REL ? NW : NA;
    int* cnt = REL ? g_cnt_rel : g_cnt_tic;
    if (i < N) cnt[i] = 0;
}

template <int REL>
__global__ __launch_bounds__(256) void hist(const int* __restrict__ dst, int E) {
    int e4 = (blockIdx.x * blockDim.x + threadIdx.x) * 4;
    if (e4 >= E) return;
    int4 d = __ldg((const int4*)&dst[e4]);
    int* cnt = REL ? g_cnt_rel : g_cnt_tic;
    atomicAdd(&cnt[d.x], 1);
    atomicAdd(&cnt[d.y], 1);
    atomicAdd(&cnt[d.z], 1);
    atomicAdd(&cnt[d.w], 1);
}

template <int REL>
__global__ __launch_bounds__(256) void scan1() {
    const int N = REL ? NW : NA;
    const int* cnt = REL ? g_cnt_rel : g_cnt_tic;
    int* start = REL ? g_start_rel : g_start_tic;
    int* bsum = REL ? g_bsum_rel : g_bsum_tic;

    __shared__ int sh[256];
    int t = threadIdx.x;
    int base = blockIdx.x * 2048 + t * 8;
    int v[8]; int s = 0;
#pragma unroll
    for (int j = 0; j < 8; j++) {
        int idx = base + j;
        int c = (idx < N) ? cnt[idx] : 0;
        v[j] = s; s += c;
    }
    sh[t] = s;
    __syncthreads();
    int own = s;
    for (int off = 1; off < 256; off <<= 1) {
        int y = (t >= off) ? sh[t - off] : 0;
        __syncthreads();
        sh[t] += y;
        __syncthreads();
    }
    int texcl = sh[t] - own;
#pragma unroll
    for (int j = 0; j < 8; j++) {
        int idx = base + j;
        if (idx < N) start[idx] = v[j] + texcl;
    }
    if (t == 255) bsum[blockIdx.x] = sh[255];
}

template <int REL>
__global__ __launch_bounds__(128) void scan2() {
    const int NB = REL ? NB_REL : NB_TIC;
    int* bsum = REL ? g_bsum_rel : g_bsum_tic;
    __shared__ int sh[128];
    int t = threadIdx.x;
    int val = (t < NB) ? bsum[t] : 0;
    sh[t] = val;
    __syncthreads();
    for (int off = 1; off < 128; off <<= 1) {
        int y = (t >= off) ? sh[t - off] : 0;
        __syncthreads();
        sh[t] += y;
        __syncthreads();
    }
    if (t < NB) bsum[t] = sh[t] - val;
}

template <int REL>
__global__ __launch_bounds__(256) void scan3() {
    const int N = REL ? NW : NA;
    int* start = REL ? g_start_rel : g_start_tic;
    int* pos = REL ? g_pos_rel : g_pos_tic;
    const int* bsum = REL ? g_bsum_rel : g_bsum_tic;
    int add = bsum[blockIdx.x];
    int base = blockIdx.x * 2048 + threadIdx.x * 8;
#pragma unroll
    for (int j = 0; j < 8; j++) {
        int idx = base + j;
        if (idx < N) {
            int v = start[idx] + add;
            start[idx] = v;
            pos[idx] = v;
        }
    }
}

template <int REL>
__global__ __launch_bounds__(256) void reorder(const int* __restrict__ src,
                                               const int* __restrict__ dst,
                                               const float* __restrict__ we,
                                               int E) {
    int e4 = (blockIdx.x * blockDim.x + threadIdx.x) * 4;
    if (e4 >= E) return;
    int4 d = __ldg((const int4*)&dst[e4]);
    int4 s = __ldg((const int4*)&src[e4]);
    float4 w = __ldg((const float4*)&we[e4]);
    int* pos = REL ? g_pos_rel : g_pos_tic;
    u64* csr = REL ? g_csr_rel : g_csr_tic;
    int p0 = atomicAdd(&pos[d.x], 1);
    int p1 = atomicAdd(&pos[d.y], 1);
    int p2 = atomicAdd(&pos[d.z], 1);
    int p3 = atomicAdd(&pos[d.w], 1);
    csr[p0] = ((u64)__float_as_uint(w.x) << 32) | (u32)s.x;
    csr[p1] = ((u64)__float_as_uint(w.y) << 32) | (u32)s.y;
    csr[p2] = ((u64)__float_as_uint(w.z) << 32) | (u32)s.z;
    csr[p3] = ((u64)__float_as_uint(w.w) << 32) | (u32)s.w;
}

// ---------------- gather (R7 version): warp per dst row, mean ---------------
template <int REL>
__global__ __launch_bounds__(256) void gather_rows() {
    const int N = REL ? NW : NA;
    const int* start = REL ? g_start_rel : g_start_tic;
    const int* cnt = REL ? g_cnt_rel : g_cnt_tic;
    const u64* csr = REL ? g_csr_rel : g_csr_tic;
    const float* h = REL ? g_h_rel : g_h_tic;
    float* acc = REL ? g_acc_rel : g_acc_tic;

    int r = blockIdx.x * 8 + (threadIdx.x >> 5);
    int lid = threadIdx.x & 31;
    if (r >= N) return;
    int beg = start[r];
    int c = cnt[r];
    int end = beg + c;

    float ax = 0.f, ay = 0.f;
    int i = beg;
    for (; i + 4 <= end; i += 4) {
        u64 p0 = __ldg(&csr[i]);
        u64 p1 = __ldg(&csr[i + 1]);
        u64 p2 = __ldg(&csr[i + 2]);
        u64 p3 = __ldg(&csr[i + 3]);
        float2 h0 = *(const float2*)&h[(size_t)(u32)p0 * P + lid * 2];
        float2 h1 = *(const float2*)&h[(size_t)(u32)p1 * P + lid * 2];
        float2 h2 = *(const float2*)&h[(size_t)(u32)p2 * P + lid * 2];
        float2 h3 = *(const float2*)&h[(size_t)(u32)p3 * P + lid * 2];
        float w0 = __uint_as_float((u32)(p0 >> 32));
        float w1 = __uint_as_float((u32)(p1 >> 32));
        float w2 = __uint_as_float((u32)(p2 >> 32));
        float w3 = __uint_as_float((u32)(p3 >> 32));
        ax += h0.x * w0 + h1.x * w1 + h2.x * w2 + h3.x * w3;
        ay += h0.y * w0 + h1.y * w1 + h2.y * w2 + h3.y * w3;
    }
    for (; i < end; i++) {
        u64 p = __ldg(&csr[i]);
        float2 hv = *(const float2*)&h[(size_t)(u32)p * P + lid * 2];
        float w = __uint_as_float((u32)(p >> 32));
        ax += hv.x * w;
        ay += hv.y * w;
    }
    float inv = (c > 0) ? 1.0f / (float)c : 0.0f;
    float2 o; o.x = ax * inv; o.y = ay * inv;
    *(float2*)&acc[(size_t)r * P + lid * 2] = o;
}

// ---------------- tf32 mma.sync GEMM ---------------------------------------
// N_TILE=64 always now. MODE:
//   0: h_tic = x_ac @ W0            (store to g_h_tic)
//   3: h_rel = x_ac @ W0            (store to g_h_rel)
//   1: out = x @ W0 + b + acc_tic
//   2: out = 0.5*(x[:, :64] + x @ W0 + b + acc_rel)
template <int MODE>
__global__ __launch_bounds__(256) void gemm_mma(const float* __restrict__ x,
                                                const float* __restrict__ W0,
                                                const float* __restrict__ b,
                                                float* __restrict__ out,
                                                int nrows) {
    constexpr int N_TILE = 64;
    constexpr int WM = 4, WN = 2;
    constexpr int WTM = 128 / WM;       // 32
    constexpr int WTN = N_TILE / WN;    // 32
    constexpr int MT = WTM / 16;        // 2
    constexpr int NT = WTN / 8;         // 4

    __shared__ u32 A_s[128][36];
    __shared__ u32 B_s[N_TILE][36];
    __shared__ float b_s[P];

    int tid = threadIdx.x;
    int wid = tid >> 5, lid = tid & 31;
    int g = lid >> 2, t4 = lid & 3;
    int wm = wid / WN, wn = wid % WN;
    int m_warp = wm * WTM, n_warp = wn * WTN;
    int row0 = blockIdx.x * 128;

    if ((MODE == 1 || MODE == 2) && tid < P) b_s[tid] = b[tid];

    float acc[MT][NT][4];
#pragma unroll
    for (int i = 0; i < MT; i++)
#pragma unroll
        for (int j = 0; j < NT; j++)
#pragma unroll
            for (int v = 0; v < 4; v++) acc[i][j][v] = 0.f;

    for (int c = 0; c < 8; c++) {
        int k0 = c * 32;
        if (c > 0) __syncthreads();
#pragma unroll
        for (int it = 0; it < 4; it++) {
            int idx = tid + it * 256;
            int m = idx >> 3, q = idx & 7;
            float4 v = make_float4(0.f, 0.f, 0.f, 0.f);
            if (row0 + m < nrows)
                v = *(const float4*)&x[(size_t)(row0 + m) * D + k0 + q * 4];
            uint4 t;
            t.x = f2tf32(v.x); t.y = f2tf32(v.y);
            t.z = f2tf32(v.z); t.w = f2tf32(v.w);
            *(uint4*)&A_s[m][q * 4] = t;
        }
#pragma unroll
        for (int it = 0; it < N_TILE * 32 / 256; it++) {
            int i = tid + it * 256;
            int k = i / N_TILE, n = i % N_TILE;
            B_s[n][k] = f2tf32(W0[(k0 + k) * P + n]);
        }
        __syncthreads();
#pragma unroll
        for (int ks = 0; ks < 4; ks++) {
            int kk = ks * 8;
            u32 afr[MT][4];
#pragma unroll
            for (int mt = 0; mt < MT; mt++) {
                int m = m_warp + mt * 16 + g;
                afr[mt][0] = A_s[m][kk + t4];
                afr[mt][1] = A_s[m + 8][kk + t4];
                afr[mt][2] = A_s[m][kk + t4 + 4];
                afr[mt][3] = A_s[m + 8][kk + t4 + 4];
            }
            u32 bfr[NT][2];
#pragma unroll
            for (int nt = 0; nt < NT; nt++) {
                int n = n_warp + nt * 8 + g;
                bfr[nt][0] = B_s[n][kk + t4];
                bfr[nt][1] = B_s[n][kk + t4 + 4];
            }
#pragma unroll
            for (int mt = 0; mt < MT; mt++)
#pragma unroll
                for (int nt = 0; nt < NT; nt++)
                    mma_tf32(acc[mt][nt], afr[mt], bfr[nt]);
        }
    }

    if (MODE == 1 || MODE == 2) __syncthreads();

#pragma unroll
    for (int mt = 0; mt < MT; mt++) {
#pragma unroll
        for (int half = 0; half < 2; half++) {
            int r = row0 + m_warp + mt * 16 + g + half * 8;
            if (r >= nrows) continue;
            const float* accb = (MODE == 1) ? g_acc_tic :
                                (MODE == 2) ? g_acc_rel : nullptr;
#pragma unroll
            for (int nt = 0; nt < NT; nt++) {
                int col = n_warp + nt * 8 + t4 * 2;
                float v0 = acc[mt][nt][half * 2 + 0];
                float v1 = acc[mt][nt][half * 2 + 1];
                if (MODE == 0 || MODE == 3) {
                    float* dstb = (MODE == 0) ? g_h_tic : g_h_rel;
                    float2 o; o.x = v0; o.y = v1;
                    *(float2*)&dstb[(size_t)r * P + col] = o;
                } else {
                    float2 av = *(const float2*)&accb[(size_t)r * P + col];
                    v0 += b_s[col] + av.x;
                    v1 += b_s[col + 1] + av.y;
                    if (MODE == 2) {
                        float2 xv = *(const float2*)&x[(size_t)r * D + col];
                        v0 = 0.5f * (xv.x + v0);
                        v1 = 0.5f * (xv.y + v1);
                    }
                    float2 o; o.x = v0; o.y = v1;
                    *(float2*)&out[(size_t)r * P + col] = o;
                }
            }
        }
    }
}

// ---------------- launch: fork-join two-stream DAG --------------------------
//  s0: gemm_h_tic ---(waits evC)---> gather<0> -> gemm_out<0>
//  s1: tic CSR build --evC--> gemm_h_rel -> rel CSR -> gather<1> -> out<1>
extern "C" void kernel_launch(void* const* d_in, const int* in_sizes, int n_in,
                              void* d_out, int out_size) {
    const float* x_ac        = (const float*)d_in[0];
    const float* x_w         = (const float*)d_in[1];
    const int*   src_tic     = (const int*)d_in[2];
    const int*   dst_tic     = (const int*)d_in[3];
    const float* w_tic       = (const float*)d_in[4];
    const int*   src_rel     = (const int*)d_in[5];
    const int*   dst_rel     = (const int*)d_in[6];
    const float* w_rel       = (const float*)d_in[7];
    const float* W_self_tic  = (const float*)d_in[8];
    const float* W_neigh_tic = (const float*)d_in[9];
    const float* b_tic       = (const float*)d_in[10];
    const float* W_self_rel  = (const float*)d_in[11];
    const float* W_neigh_rel = (const float*)d_in[12];
    const float* b_rel       = (const float*)d_in[13];
    float* out = (float*)d_out;

    static cudaStream_t s1 = nullptr;
    static cudaEvent_t ev0 = nullptr, evC = nullptr, evD = nullptr;
    if (s1 == nullptr) {
        cudaStreamCreateWithFlags(&s1, cudaStreamNonBlocking);
        cudaEventCreateWithFlags(&ev0, cudaEventDisableTiming);
        cudaEventCreateWithFlags(&evC, cudaEventDisableTiming);
        cudaEventCreateWithFlags(&evD, cudaEventDisableTiming);
    }

    const int GRID_A = (NA + 127) / 128;
    const int GRID_W = (NW + 127) / 128;

    // fork
    cudaEventRecord(ev0, 0);
    cudaStreamWaitEvent(s1, ev0, 0);

    // s0: h_tic GEMM only (critical path)
    gemm_mma<0><<<GRID_A, 256>>>(x_ac, W_neigh_tic, nullptr, nullptr, NA);

    // s1: tic CSR build (critical-path gate for gather<0>)
    zero_cnt<0><<<(NA + 255) / 256, 256, 0, s1>>>();
    hist<0><<<(E_TIC / 4 + 255) / 256, 256, 0, s1>>>(dst_tic, E_TIC);
    scan1<0><<<NB_TIC, 256, 0, s1>>>();
    scan2<0><<<1, 128, 0, s1>>>();
    scan3<0><<<NB_TIC, 256, 0, s1>>>();
    reorder<0><<<(E_TIC / 4 + 255) / 256, 256, 0, s1>>>(src_tic, dst_tic, w_tic, E_TIC);
    cudaEventRecord(evC, s1);   // tic CSR ready

    // s0: gather<0> (needs h_tic [stream order] + tic CSR [evC]) -> out<0>
    cudaStreamWaitEvent(0, evC, 0);
    gather_rows<0><<<(NA + 7) / 8, 256>>>();
    gemm_mma<1><<<GRID_A, 256>>>(x_ac, W_self_tic, b_tic, out, NA);

    // s1 (all slack): h_rel GEMM, rel CSR build, gather<1>, out<1>
    gemm_mma<3><<<GRID_A, 256, 0, s1>>>(x_ac, W_neigh_rel, nullptr, nullptr, NA);
    zero_cnt<1><<<(NW + 255) / 256, 256, 0, s1>>>();
    hist<1><<<(E_REL / 4 + 255) / 256, 256, 0, s1>>>(dst_rel, E_REL);
    scan1<1><<<NB_REL, 256, 0, s1>>>();
    scan2<1><<<1, 128, 0, s1>>>();
    scan3<1><<<NB_REL, 256, 0, s1>>>();
    reorder<1><<<(E_REL / 4 + 255) / 256, 256, 0, s1>>>(src_rel, dst_rel, w_rel, E_REL);
    gather_rows<1><<<(NW + 7) / 8, 256, 0, s1>>>();
    gemm_mma<2><<<GRID_W, 256, 0, s1>>>(x_w, W_self_rel, b_rel,
                                        out + (size_t)NA * P, NW);

    // join
    cudaEventRecord(evD, s1);
    cudaStreamWaitEvent(0, evD, 0);
}

// round 11
// speedup vs baseline: 1.0973x; 1.0042x over previous
#include <cuda_runtime.h>
#include <cstdint>

#define NA 200000
#define NW 50000
#define D 256
#define P 64
#define E_TIC 4000000
#define E_REL 1000000

#define NB_TIC ((NA + 2047) / 2048)   // 98
#define NB_REL ((NW + 2047) / 2048)   // 25

typedef unsigned long long u64;
typedef unsigned int u32;

// ---------------- scratch (device globals: no allocation allowed) ----------
__device__ float g_h_tic[(size_t)NA * P];
__device__ float g_h_rel[(size_t)NA * P];
__device__ float g_acc_tic[(size_t)NA * P];
__device__ float g_acc_rel[(size_t)NW * P];

__device__ int  g_cnt_tic[NA];
__device__ int  g_cnt_rel[NW];
__device__ int  g_start_tic[NA];
__device__ int  g_start_rel[NW];
__device__ int  g_pos_tic[NA];
__device__ int  g_pos_rel[NW];
__device__ int  g_bsum_tic[128];
__device__ int  g_bsum_rel[128];
__device__ u64  g_csr_tic[E_TIC];           // packed (w<<32 | src)
__device__ u64  g_csr_rel[E_REL];

// ---------------- helpers ---------------------------------------------------
__device__ __forceinline__ u32 f2tf32(float f) {
    u32 o; asm("cvt.rna.tf32.f32 %0, %1;" : "=r"(o) : "f"(f)); return o;
}

__device__ __forceinline__ void mma_tf32(float* c, const u32* a, const u32* b) {
    asm volatile(
        "mma.sync.aligned.m16n8k8.row.col.f32.tf32.tf32.f32 "
        "{%0,%1,%2,%3}, {%4,%5,%6,%7}, {%8,%9}, {%0,%1,%2,%3};"
        : "+f"(c[0]), "+f"(c[1]), "+f"(c[2]), "+f"(c[3])
        : "r"(a[0]), "r"(a[1]), "r"(a[2]), "r"(a[3]), "r"(b[0]), "r"(b[1]));
}

// ---------------- CSR build --------------------------------------------------
template <int REL>
__global__ __launch_bounds__(256) void zero_cnt() {
    int i = blockIdx.x * blockDim.x + threadIdx.x;
    const int N = REL ? NW : NA;
    int* cnt = REL ? g_cnt_rel : g_cnt_tic;
    if (i < N) cnt[i] = 0;
}

template <int REL>
__global__ __launch_bounds__(256) void hist(const int* __restrict__ dst, int E) {
    int e4 = (blockIdx.x * blockDim.x + threadIdx.x) * 4;
    if (e4 >= E) return;
    int4 d = __ldg((const int4*)&dst[e4]);
    int* cnt = REL ? g_cnt_rel : g_cnt_tic;
    atomicAdd(&cnt[d.x], 1);
    atomicAdd(&cnt[d.y], 1);
    atomicAdd(&cnt[d.z], 1);
    atomicAdd(&cnt[d.w], 1);
}

template <int REL>
__global__ __launch_bounds__(256) void scan1() {
    const int N = REL ? NW : NA;
    const int* cnt = REL ? g_cnt_rel : g_cnt_tic;
    int* start = REL ? g_start_rel : g_start_tic;
    int* bsum = REL ? g_bsum_rel : g_bsum_tic;

    __shared__ int sh[256];
    int t = threadIdx.x;
    int base = blockIdx.x * 2048 + t * 8;
    int v[8]; int s = 0;
#pragma unroll
    for (int j = 0; j < 8; j++) {
        int idx = base + j;
        int c = (idx < N) ? cnt[idx] : 0;
        v[j] = s; s += c;
    }
    sh[t] = s;
    __syncthreads();
    int own = s;
    for (int off = 1; off < 256; off <<= 1) {
        int y = (t >= off) ? sh[t - off] : 0;
        __syncthreads();
        sh[t] += y;
        __syncthreads();
    }
    int texcl = sh[t] - own;
#pragma unroll
    for (int j = 0; j < 8; j++) {
        int idx = base + j;
        if (idx < N) start[idx] = v[j] + texcl;
    }
    if (t == 255) bsum[blockIdx.x] = sh[255];
}

template <int REL>
__global__ __launch_bounds__(128) void scan2() {
    const int NB = REL ? NB_REL : NB_TIC;
    int* bsum = REL ? g_bsum_rel : g_bsum_tic;
    __shared__ int sh[128];
    int t = threadIdx.x;
    int val = (t < NB) ? bsum[t] : 0;
    sh[t] = val;
    __syncthreads();
    for (int off = 1; off < 128; off <<= 1) {
        int y = (t >= off) ? sh[t - off] : 0;
        __syncthreads();
        sh[t] += y;
        __syncthreads();
    }
    if (t < NB) bsum[t] = sh[t] - val;
}

template <int REL>
__global__ __launch_bounds__(256) void scan3() {
    const int N = REL ? NW : NA;
    int* start = REL ? g_start_rel : g_start_tic;
    int* pos = REL ? g_pos_rel : g_pos_tic;
    const int* bsum = REL ? g_bsum_rel : g_bsum_tic;
    int add = bsum[blockIdx.x];
    int base = blockIdx.x * 2048 + threadIdx.x * 8;
#pragma unroll
    for (int j = 0; j < 8; j++) {
        int idx = base + j;
        if (idx < N) {
            int v = start[idx] + add;
            start[idx] = v;
            pos[idx] = v;
        }
    }
}

template <int REL>
__global__ __launch_bounds__(256) void reorder(const int* __restrict__ src,
                                               const int* __restrict__ dst,
                                               const float* __restrict__ we,
                                               int E) {
    int e4 = (blockIdx.x * blockDim.x + threadIdx.x) * 4;
    if (e4 >= E) return;
    int4 d = __ldg((const int4*)&dst[e4]);
    int4 s = __ldg((const int4*)&src[e4]);
    float4 w = __ldg((const float4*)&we[e4]);
    int* pos = REL ? g_pos_rel : g_pos_tic;
    u64* csr = REL ? g_csr_rel : g_csr_tic;
    int p0 = atomicAdd(&pos[d.x], 1);
    int p1 = atomicAdd(&pos[d.y], 1);
    int p2 = atomicAdd(&pos[d.z], 1);
    int p3 = atomicAdd(&pos[d.w], 1);
    csr[p0] = ((u64)__float_as_uint(w.x) << 32) | (u32)s.x;
    csr[p1] = ((u64)__float_as_uint(w.y) << 32) | (u32)s.y;
    csr[p2] = ((u64)__float_as_uint(w.z) << 32) | (u32)s.z;
    csr[p3] = ((u64)__float_as_uint(w.w) << 32) | (u32)s.w;
}

// ---------------- gather: warp per dst row, mean ----------------------------
template <int REL>
__global__ __launch_bounds__(256) void gather_rows() {
    const int N = REL ? NW : NA;
    const int* start = REL ? g_start_rel : g_start_tic;
    const int* cnt = REL ? g_cnt_rel : g_cnt_tic;
    const u64* csr = REL ? g_csr_rel : g_csr_tic;
    const float* h = REL ? g_h_rel : g_h_tic;
    float* acc = REL ? g_acc_rel : g_acc_tic;

    int r = blockIdx.x * 8 + (threadIdx.x >> 5);
    int lid = threadIdx.x & 31;
    if (r >= N) return;
    int beg = start[r];
    int c = cnt[r];
    int end = beg + c;

    float ax = 0.f, ay = 0.f;
    int i = beg;
    for (; i + 4 <= end; i += 4) {
        u64 p0 = __ldg(&csr[i]);
        u64 p1 = __ldg(&csr[i + 1]);
        u64 p2 = __ldg(&csr[i + 2]);
        u64 p3 = __ldg(&csr[i + 3]);
        float2 h0 = *(const float2*)&h[(size_t)(u32)p0 * P + lid * 2];
        float2 h1 = *(const float2*)&h[(size_t)(u32)p1 * P + lid * 2];
        float2 h2 = *(const float2*)&h[(size_t)(u32)p2 * P + lid * 2];
        float2 h3 = *(const float2*)&h[(size_t)(u32)p3 * P + lid * 2];
        float w0 = __uint_as_float((u32)(p0 >> 32));
        float w1 = __uint_as_float((u32)(p1 >> 32));
        float w2 = __uint_as_float((u32)(p2 >> 32));
        float w3 = __uint_as_float((u32)(p3 >> 32));
        ax += h0.x * w0 + h1.x * w1 + h2.x * w2 + h3.x * w3;
        ay += h0.y * w0 + h1.y * w1 + h2.y * w2 + h3.y * w3;
    }
    for (; i < end; i++) {
        u64 p = __ldg(&csr[i]);
        float2 hv = *(const float2*)&h[(size_t)(u32)p * P + lid * 2];
        float w = __uint_as_float((u32)(p >> 32));
        ax += hv.x * w;
        ay += hv.y * w;
    }
    float inv = (c > 0) ? 1.0f / (float)c : 0.0f;
    float2 o; o.x = ax * inv; o.y = ay * inv;
    *(float2*)&acc[(size_t)r * P + lid * 2] = o;
}

// ---------------- epilogues -------------------------------------------------
// out_ac += acc_tic (elementwise, vectorized)
__global__ __launch_bounds__(256) void epi_ac(float* __restrict__ out) {
    int i = blockIdx.x * blockDim.x + threadIdx.x;
    const int TOT = NA * P / 4;
    if (i >= TOT) return;
    float4 o = ((const float4*)out)[i];
    float4 a = ((const float4*)g_acc_tic)[i];
    o.x += a.x; o.y += a.y; o.z += a.z; o.w += a.w;
    ((float4*)out)[i] = o;
}

// out_w = 0.5 * (x_w[:, :64] + out_w + acc_rel)
__global__ __launch_bounds__(256) void epi_w(const float* __restrict__ x,
                                             float* __restrict__ out) {
    int i = blockIdx.x * blockDim.x + threadIdx.x;
    const int TOT = NW * (P / 4);
    if (i >= TOT) return;
    int r = i >> 4, q = i & 15;
    float4 o = ((const float4*)out)[i];
    float4 a = ((const float4*)g_acc_rel)[i];
    float4 xv = *(const float4*)&x[(size_t)r * D + q * 4];
    o.x = 0.5f * (xv.x + o.x + a.x);
    o.y = 0.5f * (xv.y + o.y + a.y);
    o.z = 0.5f * (xv.z + o.z + a.z);
    o.w = 0.5f * (xv.w + o.w + a.w);
    ((float4*)out)[i] = o;
}

// ---------------- tf32 mma.sync GEMM ---------------------------------------
// MODE 0: h_tic = x @ W0           MODE 3: h_rel = x @ W0
// MODE 1: out  = x @ W0 + b        (raw self-GEMM; aggregation added by epi)
template <int MODE>
__global__ __launch_bounds__(256) void gemm_mma(const float* __restrict__ x,
                                                const float* __restrict__ W0,
                                                const float* __restrict__ b,
                                                float* __restrict__ out,
                                                int nrows) {
    constexpr int N_TILE = 64;
    constexpr int WM = 4, WN = 2;
    constexpr int WTM = 128 / WM;       // 32
    constexpr int WTN = N_TILE / WN;    // 32
    constexpr int MT = WTM / 16;        // 2
    constexpr int NT = WTN / 8;         // 4

    __shared__ u32 A_s[128][36];
    __shared__ u32 B_s[N_TILE][36];
    __shared__ float b_s[P];

    int tid = threadIdx.x;
    int wid = tid >> 5, lid = tid & 31;
    int g = lid >> 2, t4 = lid & 3;
    int wm = wid / WN, wn = wid % WN;
    int m_warp = wm * WTM, n_warp = wn * WTN;
    int row0 = blockIdx.x * 128;

    if (MODE == 1 && tid < P) b_s[tid] = b[tid];

    float acc[MT][NT][4];
#pragma unroll
    for (int i = 0; i < MT; i++)
#pragma unroll
        for (int j = 0; j < NT; j++)
#pragma unroll
            for (int v = 0; v < 4; v++) acc[i][j][v] = 0.f;

    for (int c = 0; c < 8; c++) {
        int k0 = c * 32;
        if (c > 0) __syncthreads();
#pragma unroll
        for (int it = 0; it < 4; it++) {
            int idx = tid + it * 256;
            int m = idx >> 3, q = idx & 7;
            float4 v = make_float4(0.f, 0.f, 0.f, 0.f);
            if (row0 + m < nrows)
                v = *(const float4*)&x[(size_t)(row0 + m) * D + k0 + q * 4];
            uint4 t;
            t.x = f2tf32(v.x); t.y = f2tf32(v.y);
            t.z = f2tf32(v.z); t.w = f2tf32(v.w);
            *(uint4*)&A_s[m][q * 4] = t;
        }
#pragma unroll
        for (int it = 0; it < N_TILE * 32 / 256; it++) {
            int i = tid + it * 256;
            int k = i / N_TILE, n = i % N_TILE;
            B_s[n][k] = f2tf32(W0[(k0 + k) * P + n]);
        }
        __syncthreads();
#pragma unroll
        for (int ks = 0; ks < 4; ks++) {
            int kk = ks * 8;
            u32 afr[MT][4];
#pragma unroll
            for (int mt = 0; mt < MT; mt++) {
                int m = m_warp + mt * 16 + g;
                afr[mt][0] = A_s[m][kk + t4];
                afr[mt][1] = A_s[m + 8][kk + t4];
                afr[mt][2] = A_s[m][kk + t4 + 4];
                afr[mt][3] = A_s[m + 8][kk + t4 + 4];
            }
            u32 bfr[NT][2];
#pragma unroll
            for (int nt = 0; nt < NT; nt++) {
                int n = n_warp + nt * 8 + g;
                bfr[nt][0] = B_s[n][kk + t4];
                bfr[nt][1] = B_s[n][kk + t4 + 4];
            }
#pragma unroll
            for (int mt = 0; mt < MT; mt++)
#pragma unroll
                for (int nt = 0; nt < NT; nt++)
                    mma_tf32(acc[mt][nt], afr[mt], bfr[nt]);
        }
    }

    if (MODE == 1) __syncthreads();

#pragma unroll
    for (int mt = 0; mt < MT; mt++) {
#pragma unroll
        for (int half = 0; half < 2; half++) {
            int r = row0 + m_warp + mt * 16 + g + half * 8;
            if (r >= nrows) continue;
#pragma unroll
            for (int nt = 0; nt < NT; nt++) {
                int col = n_warp + nt * 8 + t4 * 2;
                float v0 = acc[mt][nt][half * 2 + 0];
                float v1 = acc[mt][nt][half * 2 + 1];
                if (MODE == 0 || MODE == 3) {
                    float* dstb = (MODE == 0) ? g_h_tic : g_h_rel;
                    float2 o; o.x = v0; o.y = v1;
                    *(float2*)&dstb[(size_t)r * P + col] = o;
                } else {
                    float2 o; o.x = v0 + b_s[col]; o.y = v1 + b_s[col + 1];
                    *(float2*)&out[(size_t)r * P + col] = o;
                }
            }
        }
    }
}

// ---------------- launch: 3-stream DAG --------------------------------------
//  s0: h_tic GEMM --evH--> [wait evC] gather<0> --> [wait evS0] epi_ac
//  s1: tic CSR --evC--> h_rel GEMM -> rel CSR -> gather<1> -> [wait evS1] epi_w
//  s2: [wait evH] selfgemm<0> --evS0--> selfgemm_w --evS1
extern "C" void kernel_launch(void* const* d_in, const int* in_sizes, int n_in,
                              void* d_out, int out_size) {
    const float* x_ac        = (const float*)d_in[0];
    const float* x_w         = (const float*)d_in[1];
    const int*   src_tic     = (const int*)d_in[2];
    const int*   dst_tic     = (const int*)d_in[3];
    const float* w_tic       = (const float*)d_in[4];
    const int*   src_rel     = (const int*)d_in[5];
    const int*   dst_rel     = (const int*)d_in[6];
    const float* w_rel       = (const float*)d_in[7];
    const float* W_self_tic  = (const float*)d_in[8];
    const float* W_neigh_tic = (const float*)d_in[9];
    const float* b_tic       = (const float*)d_in[10];
    const float* W_self_rel  = (const float*)d_in[11];
    const float* W_neigh_rel = (const float*)d_in[12];
    const float* b_rel       = (const float*)d_in[13];
    float* out = (float*)d_out;

    static cudaStream_t s1 = nullptr, s2 = nullptr;
    static cudaEvent_t ev0 = nullptr, evC = nullptr, evH = nullptr,
                       evS0 = nullptr, evS1 = nullptr, evD = nullptr;
    if (s1 == nullptr) {
        cudaStreamCreateWithFlags(&s1, cudaStreamNonBlocking);
        cudaStreamCreateWithFlags(&s2, cudaStreamNonBlocking);
        cudaEventCreateWithFlags(&ev0, cudaEventDisableTiming);
        cudaEventCreateWithFlags(&evC, cudaEventDisableTiming);
        cudaEventCreateWithFlags(&evH, cudaEventDisableTiming);
        cudaEventCreateWithFlags(&evS0, cudaEventDisableTiming);
        cudaEventCreateWithFlags(&evS1, cudaEventDisableTiming);
        cudaEventCreateWithFlags(&evD, cudaEventDisableTiming);
    }

    const int GRID_A = (NA + 127) / 128;
    const int GRID_W = (NW + 127) / 128;

    // fork
    cudaEventRecord(ev0, 0);
    cudaStreamWaitEvent(s1, ev0, 0);
    cudaStreamWaitEvent(s2, ev0, 0);

    // s0: h_tic GEMM (critical path head)
    gemm_mma<0><<<GRID_A, 256>>>(x_ac, W_neigh_tic, nullptr, nullptr, NA);
    cudaEventRecord(evH, 0);

    // s1: tic CSR build
    zero_cnt<0><<<(NA + 255) / 256, 256, 0, s1>>>();
    hist<0><<<(E_TIC / 4 + 255) / 256, 256, 0, s1>>>(dst_tic, E_TIC);
    scan1<0><<<NB_TIC, 256, 0, s1>>>();
    scan2<0><<<1, 128, 0, s1>>>();
    scan3<0><<<NB_TIC, 256, 0, s1>>>();
    reorder<0><<<(E_TIC / 4 + 255) / 256, 256, 0, s1>>>(src_tic, dst_tic, w_tic, E_TIC);
    cudaEventRecord(evC, s1);   // tic CSR ready

    // s2: self-GEMMs (start after h_tic frees the tensor pipes)
    cudaStreamWaitEvent(s2, evH, 0);
    gemm_mma<1><<<GRID_A, 256, 0, s2>>>(x_ac, W_self_tic, b_tic, out, NA);
    cudaEventRecord(evS0, s2);
    gemm_mma<1><<<GRID_W, 256, 0, s2>>>(x_w, W_self_rel, b_rel,
                                        out + (size_t)NA * P, NW);
    cudaEventRecord(evS1, s2);

    // s0: gather<0> (needs h_tic [stream order] + tic CSR [evC]) -> epi_ac
    cudaStreamWaitEvent(0, evC, 0);
    gather_rows<0><<<(NA + 7) / 8, 256>>>();
    cudaStreamWaitEvent(0, evS0, 0);
    epi_ac<<<(NA * P / 4 + 255) / 256, 256>>>(out);

    // s1: h_rel GEMM, rel CSR, gather<1>, epi_w
    gemm_mma<3><<<GRID_A, 256, 0, s1>>>(x_ac, W_neigh_rel, nullptr, nullptr, NA);
    zero_cnt<1><<<(NW + 255) / 256, 256, 0, s1>>>();
    hist<1><<<(E_REL / 4 + 255) / 256, 256, 0, s1>>>(dst_rel, E_REL);
    scan1<1><<<NB_REL, 256, 0, s1>>>();
    scan2<1><<<1, 128, 0, s1>>>();
    scan3<1><<<NB_REL, 256, 0, s1>>>();
    reorder<1><<<(E_REL / 4 + 255) / 256, 256, 0, s1>>>(src_rel, dst_rel, w_rel, E_REL);
    gather_rows<1><<<(NW + 7) / 8, 256, 0, s1>>>();
    cudaStreamWaitEvent(s1, evS1, 0);
    epi_w<<<(NW * (P / 4) + 255) / 256, 256, 0, s1>>>(x_w, out + (size_t)NA * P);

    // join
    cudaEventRecord(evD, s1);
    cudaStreamWaitEvent(0, evD, 0);
}